// round 3
// baseline (speedup 1.0000x reference)
#include <cuda_runtime.h>

// Hamilton product of quaternions packed in the last dim (w, x, y, z).
// Shapes: q1, q2: (32, 4096, 64, 4) fp32 -> 8,388,608 quaternions.
// HBM-bound streaming op. Persistent single-wave grid (148 SMs x 8 CTAs),
// grid-stride loop, 4 quaternions per thread per iteration with
// front-batched LDG.128 (MLP_p1 = 8), streaming cache hints (no reuse).

#define QPT 4
#define TPB 256
#define NBLOCKS (148 * 8)   // exactly one wave on GB300 (152 SMs; 148 keeps
                            // a clean single wave even if some SMs are busy)

__device__ __forceinline__ float4 hprod(float4 a, float4 b) {
    float4 r;
    r.x = a.x * b.x - a.y * b.y - a.z * b.z - a.w * b.w;  // w
    r.y = a.x * b.y + a.y * b.x + a.z * b.w - a.w * b.z;  // x
    r.z = a.x * b.z - a.y * b.w + a.z * b.x + a.w * b.y;  // y
    r.w = a.x * b.w + a.y * b.z - a.z * b.y + a.w * b.x;  // z
    return r;
}

__global__ void __launch_bounds__(TPB) hamilton_kernel(
    const float4* __restrict__ q1,
    const float4* __restrict__ q2,
    float4* __restrict__ out,
    int n_quat)
{
    const int chunk = TPB * QPT;              // elements per block-iteration
    const long long stride = (long long)gridDim.x * chunk;

    for (long long base0 = (long long)blockIdx.x * chunk;
         base0 < n_quat; base0 += stride) {

        int base = (int)base0 + threadIdx.x;

        if (base0 + chunk <= n_quat) {
            // Fast path: front-batch all 8 loads for max MLP.
            float4 a[QPT], b[QPT];
#pragma unroll
            for (int k = 0; k < QPT; k++) a[k] = __ldcs(&q1[base + k * TPB]);
#pragma unroll
            for (int k = 0; k < QPT; k++) b[k] = __ldcs(&q2[base + k * TPB]);
#pragma unroll
            for (int k = 0; k < QPT; k++)
                __stcs(&out[base + k * TPB], hprod(a[k], b[k]));
        } else {
#pragma unroll
            for (int k = 0; k < QPT; k++) {
                int i = base + k * TPB;
                if (i < n_quat)
                    __stcs(&out[i], hprod(__ldcs(&q1[i]), __ldcs(&q2[i])));
            }
        }
    }
}

extern "C" void kernel_launch(void* const* d_in, const int* in_sizes, int n_in,
                              void* d_out, int out_size) {
    const float4* q1 = (const float4*)d_in[0];
    const float4* q2 = (const float4*)d_in[1];
    float4* out = (float4*)d_out;

    int n_quat = in_sizes[0] / 4;  // 8,388,608

    hamilton_kernel<<<NBLOCKS, TPB>>>(q1, q2, out, n_quat);
}

// round 4
// speedup vs baseline: 1.0341x; 1.0341x over previous
#include <cuda_runtime.h>

// Hamilton product of quaternions packed in the last dim (w, x, y, z).
// Shapes: q1, q2: (32, 4096, 64, 4) fp32 -> 8,388,608 quaternions.
// HBM-bound streaming op. 4 quaternions per thread, front-batched LDG.128
// (MLP_p1 = 8). n_quat = 8192 * 1024 exactly -> branch-free body.
// Streaming store hint (__stcs): output never re-read.

#define QPT 4
#define TPB 256

__device__ __forceinline__ float4 hprod(float4 a, float4 b) {
    float4 r;
    r.x = a.x * b.x - a.y * b.y - a.z * b.z - a.w * b.w;  // w
    r.y = a.x * b.y + a.y * b.x + a.z * b.w - a.w * b.z;  // x
    r.z = a.x * b.z - a.y * b.w + a.z * b.x + a.w * b.y;  // y
    r.w = a.x * b.w + a.y * b.z - a.z * b.y + a.w * b.x;  // z
    return r;
}

__global__ void __launch_bounds__(TPB) hamilton_kernel(
    const float4* __restrict__ q1,
    const float4* __restrict__ q2,
    float4* __restrict__ out)
{
    int base = blockIdx.x * (TPB * QPT) + threadIdx.x;

    float4 a[QPT], b[QPT];
#pragma unroll
    for (int k = 0; k < QPT; k++) a[k] = q1[base + k * TPB];
#pragma unroll
    for (int k = 0; k < QPT; k++) b[k] = q2[base + k * TPB];
#pragma unroll
    for (int k = 0; k < QPT; k++)
        __stcs(&out[base + k * TPB], hprod(a[k], b[k]));
}

// Fallback kernel in case the element count ever isn't divisible by the tile
// (not hit for this problem's shape, but keeps kernel_launch correct for any n).
__global__ void __launch_bounds__(TPB) hamilton_kernel_tail(
    const float4* __restrict__ q1,
    const float4* __restrict__ q2,
    float4* __restrict__ out,
    int start, int n_quat)
{
    int i = start + blockIdx.x * TPB + threadIdx.x;
    if (i < n_quat) __stcs(&out[i], hprod(q1[i], q2[i]));
}

extern "C" void kernel_launch(void* const* d_in, const int* in_sizes, int n_in,
                              void* d_out, int out_size) {
    const float4* q1 = (const float4*)d_in[0];
    const float4* q2 = (const float4*)d_in[1];
    float4* out = (float4*)d_out;

    int n_quat = in_sizes[0] / 4;        // 8,388,608
    int per_block = TPB * QPT;           // 1024
    int full_blocks = n_quat / per_block;  // 8192 (exact for this shape)
    int covered = full_blocks * per_block;

    if (full_blocks > 0)
        hamilton_kernel<<<full_blocks, TPB>>>(q1, q2, out);

    int rem = n_quat - covered;
    if (rem > 0) {
        int tail_blocks = (rem + TPB - 1) / TPB;
        hamilton_kernel_tail<<<tail_blocks, TPB>>>(q1, q2, out, covered, n_quat);
    }
}